// round 1
// baseline (speedup 1.0000x reference)
#include <cuda_runtime.h>
#include <mma.h>
#include <math.h>
#include <stdint.h>

using namespace nvcuda;

// ---------------- problem constants ----------------
#define BB    2
#define SEQ   2048
#define DMODEL 2048
#define HKN   16
#define HVN   32
#define DKD   128
#define DVD   128
#define KDIM  2048           // HKN*DKD
#define VDIM  4096           // HVN*DVD
#define CONVD 8192           // 2*KDIM + VDIM
#define BSTOK (BB*SEQ)       // 4096 tokens

// ---------------- scratch (static device globals; no allocs) ----------------
__device__ float g_mixed[(size_t)BSTOK * CONVD];   // 33.5M f32
__device__ float g_z    [(size_t)BSTOK * VDIM];    // 16.8M
__device__ float g_q    [(size_t)BSTOK * KDIM];    // 8.4M (l2-normed, *DK^-0.5)
__device__ float g_k    [(size_t)BSTOK * KDIM];    // 8.4M (l2-normed)
__device__ float g_v    [(size_t)BSTOK * VDIM];    // 16.8M
__device__ float g_eg   [(size_t)BSTOK * HVN];     // exp(g) per (token, head)
__device__ float g_beta [(size_t)BSTOK * HVN];
__device__ float g_core [(size_t)BSTOK * VDIM];    // scan out, then gated in-place

// =====================================================================
// GEMM: C[M,N] = A[M,K] @ B[K,N], row-major, tf32 tensor cores (wmma).
// Requires M%128==0, N%128==0, K%32==0 (true for all calls here).
// =====================================================================
#define GBM 128
#define GBN 128
#define GBK 32
#define GAKP 36   // padded lda for As (36 floats = 144B, multiple of 16B)

__global__ __launch_bounds__(256) void gemm_tf32(
    const float* __restrict__ A, const float* __restrict__ B,
    float* __restrict__ C, int M, int N, int K)
{
    __shared__ __align__(16) float As[GBM * GAKP];
    __shared__ __align__(16) float Bs[GBK * GBN];

    const int tid = threadIdx.x;
    const int bm0 = blockIdx.y * GBM;
    const int bn0 = blockIdx.x * GBN;
    const int wid = tid >> 5;
    const int wm  = (wid >> 2) * 64;   // warp row offset in tile (0 or 64)
    const int wn  = (wid & 3) * 32;    // warp col offset (0,32,64,96)

    wmma::fragment<wmma::accumulator, 16, 16, 8, float> acc[4][2];
    #pragma unroll
    for (int i = 0; i < 4; i++)
        #pragma unroll
        for (int j = 0; j < 2; j++)
            wmma::fill_fragment(acc[i][j], 0.0f);

    for (int kt = 0; kt < K; kt += GBK) {
        // load A tile 128x32 (float4), convert to tf32, store transposable row-major
        #pragma unroll
        for (int t = 0; t < 4; t++) {
            int j  = tid + t * 256;
            int r  = j >> 3;
            int c4 = (j & 7) * 4;
            float4 va = *(const float4*)(A + (size_t)(bm0 + r) * K + kt + c4);
            float* d = &As[r * GAKP + c4];
            d[0] = wmma::__float_to_tf32(va.x);
            d[1] = wmma::__float_to_tf32(va.y);
            d[2] = wmma::__float_to_tf32(va.z);
            d[3] = wmma::__float_to_tf32(va.w);
        }
        // load B tile 32x128
        #pragma unroll
        for (int t = 0; t < 4; t++) {
            int j  = tid + t * 256;
            int r  = j >> 5;
            int c4 = (j & 31) * 4;
            float4 vb = *(const float4*)(B + (size_t)(kt + r) * N + bn0 + c4);
            vb.x = wmma::__float_to_tf32(vb.x);
            vb.y = wmma::__float_to_tf32(vb.y);
            vb.z = wmma::__float_to_tf32(vb.z);
            vb.w = wmma::__float_to_tf32(vb.w);
            *(float4*)&Bs[r * GBN + c4] = vb;
        }
        __syncthreads();

        #pragma unroll
        for (int kk = 0; kk < GBK; kk += 8) {
            wmma::fragment<wmma::matrix_a, 16, 16, 8, wmma::precision::tf32, wmma::row_major> af[4];
            wmma::fragment<wmma::matrix_b, 16, 16, 8, wmma::precision::tf32, wmma::row_major> bf[2];
            #pragma unroll
            for (int i = 0; i < 4; i++)
                wmma::load_matrix_sync(af[i], &As[(wm + i * 16) * GAKP + kk], GAKP);
            #pragma unroll
            for (int j = 0; j < 2; j++)
                wmma::load_matrix_sync(bf[j], &Bs[kk * GBN + wn + j * 16], GBN);
            #pragma unroll
            for (int i = 0; i < 4; i++)
                #pragma unroll
                for (int j = 0; j < 2; j++)
                    wmma::mma_sync(acc[i][j], af[i], bf[j], acc[i][j]);
        }
        __syncthreads();
    }

    #pragma unroll
    for (int i = 0; i < 4; i++)
        #pragma unroll
        for (int j = 0; j < 2; j++)
            wmma::store_matrix_sync(C + (size_t)(bm0 + wm + i * 16) * N + bn0 + wn + j * 16,
                                    acc[i][j], N, wmma::mem_row_major);
}

// =====================================================================
// b/a projections (N=32 each) fused with beta = sigmoid(b),
// eg = exp(-exp(A_log)*softplus(a + dt_bias)).  One block per token.
// =====================================================================
__global__ __launch_bounds__(64) void proj_ba_kernel(
    const float* __restrict__ X, const float* __restrict__ wb,
    const float* __restrict__ wa, const float* __restrict__ dt_bias,
    const float* __restrict__ A_log,
    float* __restrict__ beta, float* __restrict__ eg)
{
    __shared__ float xs[DMODEL];
    const int bs = blockIdx.x;
    const int tid = threadIdx.x;
    for (int t = tid; t < DMODEL; t += 64)
        xs[t] = X[(size_t)bs * DMODEL + t];
    __syncthreads();

    float acc = 0.0f;
    if (tid < 32) {
        const float* w = wb + tid;
        #pragma unroll 4
        for (int d = 0; d < DMODEL; d++) acc += xs[d] * w[d * 32];
        beta[(size_t)bs * HVN + tid] = 1.0f / (1.0f + expf(-acc));
    } else {
        const int h = tid - 32;
        const float* w = wa + h;
        #pragma unroll 4
        for (int d = 0; d < DMODEL; d++) acc += xs[d] * w[d * 32];
        float x = acc + dt_bias[h];
        float sp = (x > 20.0f) ? x : log1pf(expf(x));
        float g = -expf(A_log[h]) * sp;
        eg[(size_t)bs * HVN + h] = expf(g);
    }
}

// =====================================================================
// conv1d(K=4, causal) + silu + per-head l2norm for q and k.
// grid: (BSTOK, 2*HKN)  block: 128 (one thread per DK channel)
// =====================================================================
__global__ __launch_bounds__(128) void conv_qk_kernel(const float* __restrict__ conv_w)
{
    const int bs  = blockIdx.x;
    const int hy  = blockIdx.y;
    const bool is_k = (hy >= HKN);
    const int head  = is_k ? hy - HKN : hy;
    const int lane  = threadIdx.x;
    const int c     = (is_k ? KDIM : 0) + head * DKD + lane;
    const int s     = bs % SEQ;

    const float w0 = conv_w[c * 4 + 0];
    const float w1 = conv_w[c * 4 + 1];
    const float w2 = conv_w[c * 4 + 2];
    const float w3 = conv_w[c * 4 + 3];

    const long bsl = bs;
    float acc = w3 * g_mixed[bsl * CONVD + c];
    if (s > 0) acc += w2 * g_mixed[(bsl - 1) * CONVD + c];
    if (s > 1) acc += w1 * g_mixed[(bsl - 2) * CONVD + c];
    if (s > 2) acc += w0 * g_mixed[(bsl - 3) * CONVD + c];

    float val = acc / (1.0f + expf(-acc));   // silu

    // block reduction of val^2 over 128 threads
    float ss2 = val * val;
    #pragma unroll
    for (int o = 16; o > 0; o >>= 1)
        ss2 += __shfl_xor_sync(0xffffffffu, ss2, o);
    __shared__ float red[4];
    if ((lane & 31) == 0) red[lane >> 5] = ss2;
    __syncthreads();
    float tot = red[0] + red[1] + red[2] + red[3];

    float out = val * rsqrtf(tot + 1e-6f);
    if (!is_k) out *= 0.08838834764831845f;  // DK^-0.5 folded into q

    float* dst = is_k ? g_k : g_q;
    dst[(size_t)bs * KDIM + head * DKD + lane] = out;
}

// =====================================================================
// conv1d + silu for v channels. one thread per output element.
// =====================================================================
__global__ __launch_bounds__(256) void conv_v_kernel(const float* __restrict__ conv_w)
{
    const size_t idx = (size_t)blockIdx.x * 256 + threadIdx.x;
    const int cv = (int)(idx % VDIM);
    const long bsl = (long)(idx / VDIM);
    const int s = (int)(bsl % SEQ);
    const int c = 2 * KDIM + cv;

    const float w0 = conv_w[c * 4 + 0];
    const float w1 = conv_w[c * 4 + 1];
    const float w2 = conv_w[c * 4 + 2];
    const float w3 = conv_w[c * 4 + 3];

    float acc = w3 * g_mixed[bsl * CONVD + c];
    if (s > 0) acc += w2 * g_mixed[(bsl - 1) * CONVD + c];
    if (s > 1) acc += w1 * g_mixed[(bsl - 2) * CONVD + c];
    if (s > 2) acc += w0 * g_mixed[(bsl - 3) * CONVD + c];

    g_v[idx] = acc / (1.0f + expf(-acc));
}

// =====================================================================
// Gated delta-rule scan. DV columns are independent -> split DV in 2.
// grid: B*HV*2 = 128 CTAs (one wave). block: 256.
// thread t: column v = t>>2 (local, 0..63), k-range s4 = t&3 (32 rows).
// State kept in 32 registers; v_old/o reduced across the 4-lane quad.
// =====================================================================
__global__ __launch_bounds__(256) void scan_kernel()
{
    const int blk  = blockIdx.x;
    const int half = blk & 1;
    const int hv   = (blk >> 1) & (HVN - 1);
    const int b    = blk >> 6;
    const int kh   = hv >> 1;            // GQA repeat: HV/HK = 2
    const int tid  = threadIdx.x;
    const int vcol = tid >> 2;
    const int s4   = tid & 3;

    __shared__ __align__(16) float sk[DKD];
    __shared__ __align__(16) float sq[DKD];
    __shared__ float sv[64];
    __shared__ float sgb[2];

    float St[32];
    #pragma unroll
    for (int i = 0; i < 32; i++) St[i] = 0.0f;

    for (int s = 0; s < SEQ; s++) {
        const size_t bs = (size_t)b * SEQ + s;
        if (tid < 128)       sk[tid]       = g_k[(bs * HKN + kh) * DKD + tid];
        else                 sq[tid - 128] = g_q[(bs * HKN + kh) * DKD + (tid - 128)];
        if (tid < 64)        sv[tid]       = g_v[(bs * HVN + hv) * DVD + half * 64 + tid];
        if (tid == 0) {
            sgb[0] = g_eg  [bs * HVN + hv];
            sgb[1] = g_beta[bs * HVN + hv];
        }
        __syncthreads();

        const float egv = sgb[0];
        const float bt  = sgb[1];
        const float4* k4 = (const float4*)(sk + s4 * 32);
        const float4* q4 = (const float4*)(sq + s4 * 32);

        float vold = 0.0f;
        #pragma unroll
        for (int j = 0; j < 8; j++) {
            float4 kk = k4[j];
            St[4*j+0] *= egv; vold += kk.x * St[4*j+0];
            St[4*j+1] *= egv; vold += kk.y * St[4*j+1];
            St[4*j+2] *= egv; vold += kk.z * St[4*j+2];
            St[4*j+3] *= egv; vold += kk.w * St[4*j+3];
        }
        vold += __shfl_xor_sync(0xffffffffu, vold, 1);
        vold += __shfl_xor_sync(0xffffffffu, vold, 2);

        const float delta = (sv[vcol] - vold) * bt;

        float o = 0.0f;
        #pragma unroll
        for (int j = 0; j < 8; j++) {
            float4 kk = k4[j];
            float4 qq = q4[j];
            St[4*j+0] += kk.x * delta; o += qq.x * St[4*j+0];
            St[4*j+1] += kk.y * delta; o += qq.y * St[4*j+1];
            St[4*j+2] += kk.z * delta; o += qq.z * St[4*j+2];
            St[4*j+3] += kk.w * delta; o += qq.w * St[4*j+3];
        }
        o += __shfl_xor_sync(0xffffffffu, o, 1);
        o += __shfl_xor_sync(0xffffffffu, o, 2);

        __syncthreads();   // smem reuse barrier before next step's loads

        if (s4 == 0)
            g_core[(bs * HVN + hv) * DVD + half * 64 + vcol] = o;
    }
}

// =====================================================================
// RMSNorm over DV * norm_weight * silu(z), in-place on g_core.
// grid: BSTOK*HVN blocks of 128.
// =====================================================================
__global__ __launch_bounds__(128) void rmsnorm_gate_kernel(const float* __restrict__ nw)
{
    const size_t gidx = blockIdx.x;
    const int lane = threadIdx.x;
    const size_t off = gidx * DVD + lane;

    float c = g_core[off];
    float v2 = c * c;
    #pragma unroll
    for (int o = 16; o > 0; o >>= 1)
        v2 += __shfl_xor_sync(0xffffffffu, v2, o);
    __shared__ float red[4];
    if ((lane & 31) == 0) red[lane >> 5] = v2;
    __syncthreads();
    float mean = (red[0] + red[1] + red[2] + red[3]) * (1.0f / 128.0f);

    float z = g_z[off];                       // same flat layout (B,S,HV,DV)
    float sz = z / (1.0f + expf(-z));
    g_core[off] = c * rsqrtf(mean + 1e-6f) * nw[lane] * sz;
}

// =====================================================================
// launch
// =====================================================================
extern "C" void kernel_launch(void* const* d_in, const int* in_sizes, int n_in,
                              void* d_out, int out_size)
{
    const float* X        = (const float*)d_in[0];
    const float* w_qkv    = (const float*)d_in[1];
    const float* w_z      = (const float*)d_in[2];
    const float* w_b      = (const float*)d_in[3];
    const float* w_a      = (const float*)d_in[4];
    const float* w_out    = (const float*)d_in[5];
    const float* conv_w   = (const float*)d_in[6];
    const float* dt_bias  = (const float*)d_in[7];
    const float* A_log    = (const float*)d_in[8];
    const float* norm_w   = (const float*)d_in[9];
    float* out = (float*)d_out;

    float *p_mixed, *p_z, *p_core, *p_eg, *p_beta;
    cudaGetSymbolAddress((void**)&p_mixed, g_mixed);
    cudaGetSymbolAddress((void**)&p_z,     g_z);
    cudaGetSymbolAddress((void**)&p_core,  g_core);
    cudaGetSymbolAddress((void**)&p_eg,    g_eg);
    cudaGetSymbolAddress((void**)&p_beta,  g_beta);

    // 1) mixed = X @ w_qkv   (4096 x 8192 x 2048)
    gemm_tf32<<<dim3(CONVD / GBN, BSTOK / GBM), 256>>>(X, w_qkv, p_mixed, BSTOK, CONVD, DMODEL);
    // 2) z = X @ w_z         (4096 x 4096 x 2048)
    gemm_tf32<<<dim3(VDIM / GBN, BSTOK / GBM), 256>>>(X, w_z, p_z, BSTOK, VDIM, DMODEL);
    // 3) b/a projections -> beta, exp(g)
    proj_ba_kernel<<<BSTOK, 64>>>(X, w_b, w_a, dt_bias, A_log, p_beta, p_eg);
    // 4) conv+silu+l2norm for q,k
    conv_qk_kernel<<<dim3(BSTOK, 2 * HKN), 128>>>(conv_w);
    // 5) conv+silu for v
    conv_v_kernel<<<(BSTOK * (size_t)VDIM) / 256, 256>>>(conv_w);
    // 6) gated delta-rule scan
    scan_kernel<<<BB * HVN * 2, 256>>>();
    // 7) rmsnorm * norm_weight * silu(z), in place
    rmsnorm_gate_kernel<<<BSTOK * HVN, 128>>>(norm_w);
    // 8) out = core @ w_out  (4096 x 2048 x 4096)
    gemm_tf32<<<dim3(DMODEL / GBN, BSTOK / GBM), 256>>>(p_core, w_out, out, BSTOK, DMODEL, VDIM);
}

// round 2
// speedup vs baseline: 1.3602x; 1.3602x over previous
#include <cuda_runtime.h>
#include <mma.h>
#include <math.h>
#include <stdint.h>

using namespace nvcuda;

// ---------------- problem constants ----------------
#define BB     2
#define SEQ    2048
#define DMODEL 2048
#define HKN    16
#define HVN    32
#define DKD    128
#define DVD    128
#define KDIM   2048           // HKN*DKD
#define VDIM   4096           // HVN*DVD
#define CONVD  8192           // 2*KDIM + VDIM
#define BSTOK  (BB*SEQ)       // 4096 tokens

// ---------------- scratch (static device globals; no allocs) ----------------
__device__ float g_mixed[(size_t)BSTOK * CONVD];
__device__ float g_z    [(size_t)BSTOK * VDIM];
__device__ float g_q    [(size_t)BSTOK * KDIM];
__device__ float g_k    [(size_t)BSTOK * KDIM];
__device__ float g_v    [(size_t)BSTOK * VDIM];
__device__ float g_eg   [(size_t)BSTOK * HVN];
__device__ float g_beta [(size_t)BSTOK * HVN];
__device__ float g_core [(size_t)BSTOK * VDIM];   // scan out -> gated (tf32-rounded) in-place
// tf32-rounded GEMM operands
__device__ float g_xr   [(size_t)BSTOK * DMODEL];
__device__ float g_wqkvr[(size_t)DMODEL * CONVD];
__device__ float g_wzr  [(size_t)DMODEL * VDIM];
__device__ float g_woutr[(size_t)VDIM * DMODEL];

// ---------------- cp.async helpers ----------------
__device__ __forceinline__ void cp_async16(void* smem, const void* gptr) {
    uint32_t s = (uint32_t)__cvta_generic_to_shared(smem);
    asm volatile("cp.async.cg.shared.global [%0], [%1], 16;\n" :: "r"(s), "l"(gptr));
}
__device__ __forceinline__ void cp_commit() {
    asm volatile("cp.async.commit_group;\n");
}
template<int N>
__device__ __forceinline__ void cp_wait() {
    asm volatile("cp.async.wait_group %0;\n" :: "n"(N));
}

// =====================================================================
// tf32 rounding (round-to-nearest) of a float array, vectorized.
// =====================================================================
__global__ __launch_bounds__(256) void round_tf32_kernel(
    const float* __restrict__ src, float* __restrict__ dst, int n4)
{
    int i = blockIdx.x * 256 + threadIdx.x;
    if (i < n4) {
        float4 v = ((const float4*)src)[i];
        v.x = wmma::__float_to_tf32(v.x);
        v.y = wmma::__float_to_tf32(v.y);
        v.z = wmma::__float_to_tf32(v.z);
        v.w = wmma::__float_to_tf32(v.w);
        ((float4*)dst)[i] = v;
    }
}

// =====================================================================
// GEMM: C[M,N] = A[M,K] @ B[K,N], row-major, tf32 wmma,
// 3-stage cp.async pipeline. Inputs must be pre-rounded to tf32.
// M%128==0, N%128==0, K%32==0.
// =====================================================================
#define GBM 128
#define GBN 128
#define GBK 32
#define APAD 36     // As row stride (floats), 144B (16B multiple)
#define BPAD 136    // Bs row stride (floats), 544B
#define ASTRIDE (GBM*APAD)   // 4608 floats / stage
#define BSTRIDE (GBK*BPAD)   // 4352 floats / stage
#define STAGES 3
#define GEMM_SMEM_BYTES (STAGES*(ASTRIDE+BSTRIDE)*4)  // 107520

__global__ __launch_bounds__(256) void gemm_tf32(
    const float* __restrict__ A, const float* __restrict__ B,
    float* __restrict__ C, int M, int N, int K)
{
    extern __shared__ float smem[];
    float* AsBase = smem;                       // STAGES * ASTRIDE
    float* BsBase = smem + STAGES * ASTRIDE;    // STAGES * BSTRIDE

    const int tid = threadIdx.x;
    const int bm0 = blockIdx.y * GBM;
    const int bn0 = blockIdx.x * GBN;
    const int wid = tid >> 5;
    const int wm  = (wid >> 2) * 64;
    const int wn  = (wid & 3) * 32;
    const int KT  = K / GBK;

    // per-thread load assignments (4 A-chunks + 4 B-chunks of 16B)
    int ar[4], ac[4], br[4], bc[4];
    #pragma unroll
    for (int t = 0; t < 4; t++) {
        int c = tid + t * 256;
        ar[t] = c >> 3;  ac[t] = (c & 7) * 4;
        br[t] = c >> 5;  bc[t] = (c & 31) * 4;
    }

    auto load_tile = [&](int buf, int kt) {
        const int k0 = kt * GBK;
        float* as = AsBase + buf * ASTRIDE;
        float* bs = BsBase + buf * BSTRIDE;
        #pragma unroll
        for (int t = 0; t < 4; t++)
            cp_async16(&as[ar[t] * APAD + ac[t]],
                       A + (size_t)(bm0 + ar[t]) * K + k0 + ac[t]);
        #pragma unroll
        for (int t = 0; t < 4; t++)
            cp_async16(&bs[br[t] * BPAD + bc[t]],
                       B + (size_t)(k0 + br[t]) * N + bn0 + bc[t]);
        cp_commit();
    };

    wmma::fragment<wmma::accumulator, 16, 16, 8, float> acc[4][2];
    #pragma unroll
    for (int i = 0; i < 4; i++)
        #pragma unroll
        for (int j = 0; j < 2; j++)
            wmma::fill_fragment(acc[i][j], 0.0f);

    // prologue: stages 0,1
    load_tile(0, 0);
    load_tile(1, KT > 1 ? 1 : 0);

    for (int i = 0; i < KT; i++) {
        // issue load for i+2 (clamped -> redundant harmless loads at tail)
        int nkt = i + 2 < KT ? i + 2 : KT - 1;
        load_tile((i + 2) % STAGES, nkt);
        cp_wait<2>();           // buffer i ready
        __syncthreads();

        const float* as = AsBase + (i % STAGES) * ASTRIDE;
        const float* bs = BsBase + (i % STAGES) * BSTRIDE;
        #pragma unroll
        for (int kk = 0; kk < GBK; kk += 8) {
            wmma::fragment<wmma::matrix_a, 16, 16, 8, wmma::precision::tf32, wmma::row_major> af[4];
            wmma::fragment<wmma::matrix_b, 16, 16, 8, wmma::precision::tf32, wmma::row_major> bf[2];
            #pragma unroll
            for (int x = 0; x < 4; x++)
                wmma::load_matrix_sync(af[x], &as[(wm + x * 16) * APAD + kk], APAD);
            #pragma unroll
            for (int y = 0; y < 2; y++)
                wmma::load_matrix_sync(bf[y], &bs[kk * BPAD + wn + y * 16], BPAD);
            #pragma unroll
            for (int x = 0; x < 4; x++)
                #pragma unroll
                for (int y = 0; y < 2; y++)
                    wmma::mma_sync(acc[x][y], af[x], bf[y], acc[x][y]);
        }
        __syncthreads();   // all reads of this buffer done before it is rewritten
    }

    #pragma unroll
    for (int x = 0; x < 4; x++)
        #pragma unroll
        for (int y = 0; y < 2; y++)
            wmma::store_matrix_sync(C + (size_t)(bm0 + wm + x * 16) * N + bn0 + wn + y * 16,
                                    acc[x][y], N, wmma::mem_row_major);
}

// =====================================================================
// b/a projections fused with beta=sigmoid(b), eg=exp(g).
// One block per token, 4 threads per output, quad shfl reduce.
// =====================================================================
__global__ __launch_bounds__(256) void proj_ba_kernel(
    const float* __restrict__ X, const float* __restrict__ wb,
    const float* __restrict__ wa, const float* __restrict__ dt_bias,
    const float* __restrict__ A_log,
    float* __restrict__ beta, float* __restrict__ eg)
{
    __shared__ float xs[DMODEL];
    const int bs = blockIdx.x;
    const int tid = threadIdx.x;
    #pragma unroll
    for (int t = tid; t < DMODEL; t += 256)
        xs[t] = X[(size_t)bs * DMODEL + t];
    __syncthreads();

    const int out  = tid >> 2;   // 0..63
    const int part = tid & 3;
    const bool is_b = (out < 32);
    const int h = is_b ? out : out - 32;
    const float* w = (is_b ? wb : wa) + h;

    float acc = 0.0f;
    #pragma unroll 8
    for (int d = part; d < DMODEL; d += 4)
        acc += xs[d] * w[d * 32];
    acc += __shfl_xor_sync(0xffffffffu, acc, 1);
    acc += __shfl_xor_sync(0xffffffffu, acc, 2);

    if (part == 0) {
        if (is_b) {
            beta[(size_t)bs * HVN + h] = 1.0f / (1.0f + expf(-acc));
        } else {
            float x = acc + dt_bias[h];
            float sp = (x > 20.0f) ? x : log1pf(expf(x));
            eg[(size_t)bs * HVN + h] = expf(-expf(A_log[h]) * sp);
        }
    }
}

// =====================================================================
// conv1d(K=4, causal) + silu + per-head l2norm for q and k.
// =====================================================================
__global__ __launch_bounds__(128) void conv_qk_kernel(const float* __restrict__ conv_w)
{
    const int bs  = blockIdx.x;
    const int hy  = blockIdx.y;
    const bool is_k = (hy >= HKN);
    const int head  = is_k ? hy - HKN : hy;
    const int lane  = threadIdx.x;
    const int c     = (is_k ? KDIM : 0) + head * DKD + lane;
    const int s     = bs % SEQ;

    const float w0 = conv_w[c * 4 + 0];
    const float w1 = conv_w[c * 4 + 1];
    const float w2 = conv_w[c * 4 + 2];
    const float w3 = conv_w[c * 4 + 3];

    const long bsl = bs;
    float acc = w3 * g_mixed[bsl * CONVD + c];
    if (s > 0) acc += w2 * g_mixed[(bsl - 1) * CONVD + c];
    if (s > 1) acc += w1 * g_mixed[(bsl - 2) * CONVD + c];
    if (s > 2) acc += w0 * g_mixed[(bsl - 3) * CONVD + c];

    float val = acc / (1.0f + expf(-acc));   // silu

    float ss2 = val * val;
    #pragma unroll
    for (int o = 16; o > 0; o >>= 1)
        ss2 += __shfl_xor_sync(0xffffffffu, ss2, o);
    __shared__ float red[4];
    if ((lane & 31) == 0) red[lane >> 5] = ss2;
    __syncthreads();
    float tot = red[0] + red[1] + red[2] + red[3];

    float out = val * rsqrtf(tot + 1e-6f);
    if (!is_k) out *= 0.08838834764831845f;  // DK^-0.5 folded into q

    float* dst = is_k ? g_k : g_q;
    dst[(size_t)bs * KDIM + head * DKD + lane] = out;
}

// =====================================================================
// conv1d + silu for v channels.
// =====================================================================
__global__ __launch_bounds__(256) void conv_v_kernel(const float* __restrict__ conv_w)
{
    const size_t idx = (size_t)blockIdx.x * 256 + threadIdx.x;
    const int cv = (int)(idx % VDIM);
    const long bsl = (long)(idx / VDIM);
    const int s = (int)(bsl % SEQ);
    const int c = 2 * KDIM + cv;

    const float w0 = conv_w[c * 4 + 0];
    const float w1 = conv_w[c * 4 + 1];
    const float w2 = conv_w[c * 4 + 2];
    const float w3 = conv_w[c * 4 + 3];

    float acc = w3 * g_mixed[bsl * CONVD + c];
    if (s > 0) acc += w2 * g_mixed[(bsl - 1) * CONVD + c];
    if (s > 1) acc += w1 * g_mixed[(bsl - 2) * CONVD + c];
    if (s > 2) acc += w0 * g_mixed[(bsl - 3) * CONVD + c];

    g_v[idx] = acc / (1.0f + expf(-acc));
}

// =====================================================================
// Gated delta-rule scan: double-buffered smem + register prefetch,
// ONE barrier per step. grid = B*HV*2 = 128 CTAs, 256 threads.
// =====================================================================
__global__ __launch_bounds__(256) void scan_kernel()
{
    const int blk  = blockIdx.x;
    const int half = blk & 1;
    const int hv   = (blk >> 1) & (HVN - 1);
    const int b    = blk >> 6;
    const int kh   = hv >> 1;            // GQA: HV/HK = 2
    const int tid  = threadIdx.x;
    const int vcol = tid >> 2;
    const int s4   = tid & 3;

    __shared__ __align__(16) float sk[2][DKD];
    __shared__ __align__(16) float sq[2][DKD];
    __shared__ float sv[2][64];
    __shared__ float sgb[2][2];

    float St[32];
    #pragma unroll
    for (int i = 0; i < 32; i++) St[i] = 0.0f;

    const size_t bs0 = (size_t)b * SEQ;
    float rA = 0.0f, rV = 0.0f, rG = 0.0f, rB = 0.0f;

    // prologue: load step 0, stage to buffer 0
    {
        const size_t bs = bs0;
        if (tid < 128) rA = g_k[(bs * HKN + kh) * DKD + tid];
        else           rA = g_q[(bs * HKN + kh) * DKD + (tid - 128)];
        if (tid < 64)  rV = g_v[(bs * HVN + hv) * DVD + half * 64 + tid];
        if (tid == 0) { rG = g_eg[bs * HVN + hv]; rB = g_beta[bs * HVN + hv]; }
        if (tid < 128) sk[0][tid] = rA; else sq[0][tid - 128] = rA;
        if (tid < 64)  sv[0][tid] = rV;
        if (tid == 0) { sgb[0][0] = rG; sgb[0][1] = rB; }
    }
    __syncthreads();

    for (int s = 0; s < SEQ; s++) {
        const int p = s & 1;

        // prefetch step s+1 into registers (overlaps with compute below)
        const bool more = (s + 1 < SEQ);
        if (more) {
            const size_t bs = bs0 + s + 1;
            if (tid < 128) rA = g_k[(bs * HKN + kh) * DKD + tid];
            else           rA = g_q[(bs * HKN + kh) * DKD + (tid - 128)];
            if (tid < 64)  rV = g_v[(bs * HVN + hv) * DVD + half * 64 + tid];
            if (tid == 0) { rG = g_eg[bs * HVN + hv]; rB = g_beta[bs * HVN + hv]; }
        }

        const float egv = sgb[p][0];
        const float bt  = sgb[p][1];
        const float4* k4 = (const float4*)(sk[p] + s4 * 32);
        const float4* q4 = (const float4*)(sq[p] + s4 * 32);

        float vold = 0.0f;
        #pragma unroll
        for (int j = 0; j < 8; j++) {
            float4 kk = k4[j];
            St[4*j+0] *= egv; vold += kk.x * St[4*j+0];
            St[4*j+1] *= egv; vold += kk.y * St[4*j+1];
            St[4*j+2] *= egv; vold += kk.z * St[4*j+2];
            St[4*j+3] *= egv; vold += kk.w * St[4*j+3];
        }
        vold += __shfl_xor_sync(0xffffffffu, vold, 1);
        vold += __shfl_xor_sync(0xffffffffu, vold, 2);

        const float delta = (sv[p][vcol] - vold) * bt;

        float o = 0.0f;
        #pragma unroll
        for (int j = 0; j < 8; j++) {
            float4 kk = k4[j];
            float4 qq = q4[j];
            St[4*j+0] += kk.x * delta; o += qq.x * St[4*j+0];
            St[4*j+1] += kk.y * delta; o += qq.y * St[4*j+1];
            St[4*j+2] += kk.z * delta; o += qq.z * St[4*j+2];
            St[4*j+3] += kk.w * delta; o += qq.w * St[4*j+3];
        }
        o += __shfl_xor_sync(0xffffffffu, o, 1);
        o += __shfl_xor_sync(0xffffffffu, o, 2);

        if (s4 == 0)
            g_core[((bs0 + s) * HVN + hv) * DVD + half * 64 + vcol] = o;

        // stage prefetched step into the alternate buffer
        if (more) {
            const int np = p ^ 1;
            if (tid < 128) sk[np][tid] = rA; else sq[np][tid - 128] = rA;
            if (tid < 64)  sv[np][tid] = rV;
            if (tid == 0) { sgb[np][0] = rG; sgb[np][1] = rB; }
        }
        __syncthreads();
    }
}

// =====================================================================
// RMSNorm * norm_weight * silu(z), in-place, output rounded to tf32
// (it feeds GEMM3 via cp.async).
// =====================================================================
__global__ __launch_bounds__(128) void rmsnorm_gate_kernel(const float* __restrict__ nw)
{
    const size_t gidx = blockIdx.x;
    const int lane = threadIdx.x;
    const size_t off = gidx * DVD + lane;

    float c = g_core[off];
    float v2 = c * c;
    #pragma unroll
    for (int o = 16; o > 0; o >>= 1)
        v2 += __shfl_xor_sync(0xffffffffu, v2, o);
    __shared__ float red[4];
    if ((lane & 31) == 0) red[lane >> 5] = v2;
    __syncthreads();
    float mean = (red[0] + red[1] + red[2] + red[3]) * (1.0f / 128.0f);

    float z = g_z[off];
    float sz = z / (1.0f + expf(-z));
    float r = c * rsqrtf(mean + 1e-6f) * nw[lane] * sz;
    g_core[off] = wmma::__float_to_tf32(r);
}

// =====================================================================
// launch
// =====================================================================
extern "C" void kernel_launch(void* const* d_in, const int* in_sizes, int n_in,
                              void* d_out, int out_size)
{
    const float* X        = (const float*)d_in[0];
    const float* w_qkv    = (const float*)d_in[1];
    const float* w_z      = (const float*)d_in[2];
    const float* w_b      = (const float*)d_in[3];
    const float* w_a      = (const float*)d_in[4];
    const float* w_out    = (const float*)d_in[5];
    const float* conv_w   = (const float*)d_in[6];
    const float* dt_bias  = (const float*)d_in[7];
    const float* A_log    = (const float*)d_in[8];
    const float* norm_w   = (const float*)d_in[9];
    float* out = (float*)d_out;

    float *p_mixed, *p_z, *p_core, *p_eg, *p_beta;
    float *p_xr, *p_wqkvr, *p_wzr, *p_woutr;
    cudaGetSymbolAddress((void**)&p_mixed, g_mixed);
    cudaGetSymbolAddress((void**)&p_z,     g_z);
    cudaGetSymbolAddress((void**)&p_core,  g_core);
    cudaGetSymbolAddress((void**)&p_eg,    g_eg);
    cudaGetSymbolAddress((void**)&p_beta,  g_beta);
    cudaGetSymbolAddress((void**)&p_xr,    g_xr);
    cudaGetSymbolAddress((void**)&p_wqkvr, g_wqkvr);
    cudaGetSymbolAddress((void**)&p_wzr,   g_wzr);
    cudaGetSymbolAddress((void**)&p_woutr, g_woutr);

    static int smem_set = 0;
    cudaFuncSetAttribute(gemm_tf32, cudaFuncAttributeMaxDynamicSharedMemorySize, GEMM_SMEM_BYTES);
    (void)smem_set;

    // 0) tf32-round GEMM operands
    {
        int n4;
        n4 = BSTOK * DMODEL / 4;
        round_tf32_kernel<<<(n4 + 255) / 256, 256>>>(X, p_xr, n4);
        n4 = DMODEL * CONVD / 4;
        round_tf32_kernel<<<(n4 + 255) / 256, 256>>>(w_qkv, p_wqkvr, n4);
        n4 = DMODEL * VDIM / 4;
        round_tf32_kernel<<<(n4 + 255) / 256, 256>>>(w_z, p_wzr, n4);
        n4 = VDIM * DMODEL / 4;
        round_tf32_kernel<<<(n4 + 255) / 256, 256>>>(w_out, p_woutr, n4);
    }

    // 1) mixed = X @ w_qkv
    gemm_tf32<<<dim3(CONVD / GBN, BSTOK / GBM), 256, GEMM_SMEM_BYTES>>>(
        p_xr, p_wqkvr, p_mixed, BSTOK, CONVD, DMODEL);
    // 2) z = X @ w_z
    gemm_tf32<<<dim3(VDIM / GBN, BSTOK / GBM), 256, GEMM_SMEM_BYTES>>>(
        p_xr, p_wzr, p_z, BSTOK, VDIM, DMODEL);
    // 3) b/a projections
    proj_ba_kernel<<<BSTOK, 256>>>(X, w_b, w_a, dt_bias, A_log, p_beta, p_eg);
    // 4) conv+silu+l2norm for q,k
    conv_qk_kernel<<<dim3(BSTOK, 2 * HKN), 128>>>(conv_w);
    // 5) conv+silu for v
    conv_v_kernel<<<(BSTOK * (size_t)VDIM) / 256, 256>>>(conv_w);
    // 6) gated delta-rule scan
    scan_kernel<<<BB * HVN * 2, 256>>>();
    // 7) rmsnorm * nw * silu(z) (tf32-rounded output)
    rmsnorm_gate_kernel<<<BSTOK * HVN, 128>>>(norm_w);
    // 8) out = core @ w_out
    gemm_tf32<<<dim3(DMODEL / GBN, BSTOK / GBM), 256, GEMM_SMEM_BYTES>>>(
        p_core, p_woutr, out, BSTOK, DMODEL, VDIM);
}